// round 17
// baseline (speedup 1.0000x reference)
#include <cuda_runtime.h>
#include <cuda_bf16.h>
#include <math.h>
#include <stdint.h>

// ---------------------------------------------------------------------------
// Problem constants: B=16, H=W=64, DIM=256, HEADS=8, DHEAD=32, WS=8, SHIFT=4
// N=64 tok/window, NW=64, NTOK=65536, 1024 windows total
// ---------------------------------------------------------------------------
#define NTOK 65536
#define DIMC 256
#define SCALE_Q 0.17677669529663687f

// ---------------------------------------------------------------------------
// Scratch (device globals — no allocations allowed)
// ---------------------------------------------------------------------------
__device__ __nv_bfloat16 g_x0w[(size_t)NTOK * DIMC];   // LN(x0) windowed
__device__ __nv_bfloat16 g_x1w[(size_t)NTOK * DIMC];   // LN(x1) windowed
__device__ __nv_bfloat16 g_qb [(size_t)NTOK * DIMC];   // scaled Q, bf16
__device__ __nv_bfloat16 g_kb [(size_t)NTOK * DIMC];   // K, bf16
__device__ __nv_bfloat16 g_vt [(size_t)NTOK * DIMC];   // V transposed per (w,h)
__device__ __nv_bfloat16 g_o  [(size_t)NTOK * DIMC];   // attn out (windowed)
__device__ float         g_x  [(size_t)NTOK * DIMC];   // x = shortcut + attn
__device__ __nv_bfloat16 g_xn [(size_t)NTOK * DIMC];   // LN2(x)
__device__ __nv_bfloat16 g_h  [(size_t)NTOK * 1024];   // gelu(fc1)
__device__ __nv_bfloat16 g_wb [786432];                // bf16 weights

#define WOFF_Q   0
#define WOFF_KV  65536
#define WOFF_P   196608
#define WOFF_FC1 262144
#define WOFF_FC2 524288

__device__ __forceinline__ const __nv_bfloat16* abuf(int id) {
    switch (id) {
        case 0: return g_x0w;
        case 1: return g_x1w;
        case 4: return g_o;
        case 6: return g_xn;
        default: return g_h;
    }
}
__device__ __forceinline__ float* cbuf(int id) {
    return g_x;
}
__device__ __forceinline__ __nv_bfloat16* bbuf(int id) {
    switch (id) {
        case 2: return g_qb;
        default: return g_h;
    }
}

__device__ __forceinline__ int win_to_flat(int m) {
    int w  = m >> 6, t = m & 63;
    int b  = w >> 6, wi = w & 63;
    int hs = ((wi >> 3) << 3) + (t >> 3);
    int ws = ((wi & 7) << 3) + (t & 7);
    int hh = (hs + 4) & 63;
    int ww = (ws + 4) & 63;
    return (b << 12) + (hh << 6) + ww;
}

__device__ __forceinline__ uint32_t bf2(float lo, float hi) {
    __nv_bfloat162 h = __floats2bfloat162_rn(lo, hi);
    return *(uint32_t*)&h;
}

__device__ __forceinline__ void mma_bf16(float c[4], const uint32_t a[4],
                                         uint32_t b0, uint32_t b1) {
    asm volatile(
        "mma.sync.aligned.m16n8k16.row.col.f32.bf16.bf16.f32 "
        "{%0,%1,%2,%3}, {%4,%5,%6,%7}, {%8,%9}, {%0,%1,%2,%3};\n"
        : "+f"(c[0]), "+f"(c[1]), "+f"(c[2]), "+f"(c[3])
        : "r"(a[0]), "r"(a[1]), "r"(a[2]), "r"(a[3]), "r"(b0), "r"(b1));
}

#define CP16(dst, src) \
    asm volatile("cp.async.ca.shared.global [%0], [%1], 16;" :: "r"(dst), "l"(src))

#define LDSM4(r0, r1, r2, r3, addr) \
    asm volatile("ldmatrix.sync.aligned.m8n8.x4.shared.b16 {%0,%1,%2,%3}, [%4];" \
        : "=r"(r0), "=r"(r1), "=r"(r2), "=r"(r3) : "r"(addr))

// ---------------------------------------------------------------------------
// One-shot: weights fp32 -> bf16
// ---------------------------------------------------------------------------
__global__ __launch_bounds__(256) void cvt_w_k(
    const float* __restrict__ Wq, const float* __restrict__ Wkv,
    const float* __restrict__ Wp, const float* __restrict__ Wfc1,
    const float* __restrict__ Wfc2)
{
    int i4 = blockIdx.x * 256 + threadIdx.x;
    const float* src; int off4;
    if      (i4 < 16384)  { src = Wq;   off4 = 0; }
    else if (i4 < 49152)  { src = Wkv;  off4 = 16384; }
    else if (i4 < 65536)  { src = Wp;   off4 = 49152; }
    else if (i4 < 131072) { src = Wfc1; off4 = 65536; }
    else                  { src = Wfc2; off4 = 131072; }
    float4 v = ((const float4*)src)[i4 - off4];
    ((uint2*)g_wb)[i4] = make_uint2(bf2(v.x, v.y), bf2(v.z, v.w));
}

// ---------------------------------------------------------------------------
// LN(x0), LN(x1) + roll + window partition. One warp/token. bf16 out.
// ---------------------------------------------------------------------------
__global__ __launch_bounds__(256) void ln_win_k(
    const float* __restrict__ x0, const float* __restrict__ x1,
    const float* __restrict__ g0, const float* __restrict__ b0,
    const float* __restrict__ g1, const float* __restrict__ b1)
{
    int warp = blockIdx.x * 8 + (threadIdx.x >> 5);
    int lane = threadIdx.x & 31;
    int which = warp >> 16;
    int tok   = warp & (NTOK - 1);
    int flat  = win_to_flat(tok);

    const float* src = which ? x1 : x0;
    const float* gg  = which ? g1 : g0;
    const float* bb  = which ? b1 : b0;
    __nv_bfloat16* dst = which ? g_x1w : g_x0w;

    const float4* p = (const float4*)(src + (size_t)flat * DIMC);
    float4 u = p[lane * 2], v = p[lane * 2 + 1];

    float s = u.x + u.y + u.z + u.w + v.x + v.y + v.z + v.w;
    float q = u.x*u.x + u.y*u.y + u.z*u.z + u.w*u.w
            + v.x*v.x + v.y*v.y + v.z*v.z + v.w*v.w;
    #pragma unroll
    for (int o = 16; o; o >>= 1) {
        s += __shfl_xor_sync(0xffffffffu, s, o);
        q += __shfl_xor_sync(0xffffffffu, q, o);
    }
    float mean = s * (1.0f / 256.0f);
    float var  = q * (1.0f / 256.0f) - mean * mean;
    float rstd = rsqrtf(var + 1e-5f);

    const float4* gp = (const float4*)gg;
    const float4* bp = (const float4*)bb;
    float4 gu = gp[lane * 2], gv = gp[lane * 2 + 1];
    float4 bu = bp[lane * 2], bv = bp[lane * 2 + 1];

    uint4 o4;
    o4.x = bf2((u.x - mean) * rstd * gu.x + bu.x, (u.y - mean) * rstd * gu.y + bu.y);
    o4.y = bf2((u.z - mean) * rstd * gu.z + bu.z, (u.w - mean) * rstd * gu.w + bu.w);
    o4.z = bf2((v.x - mean) * rstd * gv.x + bv.x, (v.y - mean) * rstd * gv.y + bv.y);
    o4.w = bf2((v.z - mean) * rstd * gv.z + bv.z, (v.w - mean) * rstd * gv.w + bv.w);
    ((uint4*)(dst + (size_t)tok * DIMC))[lane] = o4;
}

// ---------------------------------------------------------------------------
// LN2 of g_x -> g_xn, bf16 out
// ---------------------------------------------------------------------------
__global__ __launch_bounds__(256) void ln2_k(
    const float* __restrict__ gg, const float* __restrict__ bb)
{
    int warp = blockIdx.x * 8 + (threadIdx.x >> 5);
    int lane = threadIdx.x & 31;

    const float4* p = (const float4*)(g_x + (size_t)warp * DIMC);
    float4 u = p[lane * 2], v = p[lane * 2 + 1];

    float s = u.x + u.y + u.z + u.w + v.x + v.y + v.z + v.w;
    float q = u.x*u.x + u.y*u.y + u.z*u.z + u.w*u.w
            + v.x*v.x + v.y*v.y + v.z*v.z + v.w*v.w;
    #pragma unroll
    for (int o = 16; o; o >>= 1) {
        s += __shfl_xor_sync(0xffffffffu, s, o);
        q += __shfl_xor_sync(0xffffffffu, q, o);
    }
    float mean = s * (1.0f / 256.0f);
    float var  = q * (1.0f / 256.0f) - mean * mean;
    float rstd = rsqrtf(var + 1e-5f);

    const float4* gp = (const float4*)gg;
    const float4* bp = (const float4*)bb;
    float4 gu = gp[lane * 2], gv = gp[lane * 2 + 1];
    float4 bu = bp[lane * 2], bv = bp[lane * 2 + 1];

    uint4 o4;
    o4.x = bf2((u.x - mean) * rstd * gu.x + bu.x, (u.y - mean) * rstd * gu.y + bu.y);
    o4.y = bf2((u.z - mean) * rstd * gu.z + bu.z, (u.w - mean) * rstd * gu.w + bu.w);
    o4.z = bf2((v.x - mean) * rstd * gv.x + bv.x, (v.y - mean) * rstd * gv.y + bv.y);
    o4.w = bf2((v.z - mean) * rstd * gv.z + bv.z, (v.w - mean) * rstd * gv.w + bv.w);
    ((uint4*)(g_xn + (size_t)warp * DIMC))[lane] = o4;
}

// ---------------------------------------------------------------------------
// bf16 tensor-core GEMM: 128x128 CTA tile, 4 warps (2x2), warp tile 64x64.
// Per k-step: 4 A-LDSM.x4 + 4 B-LDSM.x4 feed 32 mmas (2.3x less smem
// traffic per flop than the 32x64 warp tile).
// ---------------------------------------------------------------------------
#define EPI_SCALE   0
#define EPI_KV      1
#define EPI_GELU    2
#define EPI_SCATTER 3
#define EPI_RESID   4

template<int EPI, bool OUTBF>
__global__ __launch_bounds__(128) void gemm_tc(
    int a_id, int w_off, const float* __restrict__ bias,
    int r_id, const float* __restrict__ r_ext,
    int c_id, float* __restrict__ c_ext,
    int N, int K, float scale)
{
    __shared__ __align__(16) uint32_t As[2][128][20];
    __shared__ __align__(16) uint32_t Bs[2][128][20];

    const __nv_bfloat16* A  = abuf(a_id);
    const __nv_bfloat16* Wm = g_wb + w_off;
    float* C = nullptr;
    if (!OUTBF && EPI != EPI_KV) C = (c_id >= 0) ? cbuf(c_id) : c_ext;
    const float* R = nullptr;
    if (EPI == EPI_SCATTER || EPI == EPI_RESID)
        R = (r_id >= 0) ? cbuf(r_id) : r_ext;

    int tid  = threadIdx.x;
    int lane = tid & 31;
    int wid  = tid >> 5;
    int wm   = wid & 1;       // warp row (64 rows each)
    int wn   = wid >> 1;      // warp col (64 cols each)
    int m0 = blockIdx.y * 128, n0 = blockIdx.x * 128;

    int lr = tid >> 2;        // 0..31
    int lc = (tid & 3) * 4;   // u32 col 0,4,8,12

    uint32_t ab  = (uint32_t)__cvta_generic_to_shared(&As[0][0][0]);
    uint32_t bb_ = (uint32_t)__cvta_generic_to_shared(&Bs[0][0][0]);

    const __nv_bfloat16* Ap = A  + (size_t)(m0 + lr) * K + lc * 2;
    const __nv_bfloat16* Wp = Wm + (size_t)(n0 + lr) * K + lc * 2;
    size_t rstep = (size_t)32 * K;     // +32 rows

    int grp = lane >> 3, rr8 = lane & 7;
    uint32_t aL0 = ab  + (((uint32_t)(wm * 64 + (grp & 1) * 8 + rr8) * 20
                          + (uint32_t)((grp >> 1) * 4)) << 2);
    uint32_t bL0 = bb_ + (((uint32_t)(wn * 64 + (grp & 1) * 8 + rr8) * 20
                          + (uint32_t)((grp >> 1) * 4)) << 2);

    float acc[4][8][4];
    #pragma unroll
    for (int a = 0; a < 4; a++)
        #pragma unroll
        for (int b = 0; b < 8; b++)
            #pragma unroll
            for (int c = 0; c < 4; c++) acc[a][b][c] = 0.0f;

    int ntile = K >> 5;
    // prologue -> buf 0
    #pragma unroll
    for (int i = 0; i < 4; i++) {
        uint32_t da = ab  + (((i * 32 + lr) * 20 + lc) << 2);
        uint32_t db = bb_ + (((i * 32 + lr) * 20 + lc) << 2);
        CP16(da, Ap + i * rstep);
        CP16(db, Wp + i * rstep);
    }
    asm volatile("cp.async.commit_group;");

    for (int t = 0; t < ntile; t++) {
        int cur = t & 1;
        if (t + 1 < ntile) {
            int kt = (t + 1) << 5;
            int nb = cur ^ 1;
            #pragma unroll
            for (int i = 0; i < 4; i++) {
                uint32_t da = ab  + (((nb * 128 + i * 32 + lr) * 20 + lc) << 2);
                uint32_t db = bb_ + (((nb * 128 + i * 32 + lr) * 20 + lc) << 2);
                CP16(da, Ap + i * rstep + kt);
                CP16(db, Wp + i * rstep + kt);
            }
            asm volatile("cp.async.commit_group;");
            asm volatile("cp.async.wait_group 1;");
        } else {
            asm volatile("cp.async.wait_group 0;");
        }
        __syncthreads();

        uint32_t aB = aL0 + cur * 10240;
        uint32_t bB = bL0 + cur * 10240;
        #pragma unroll
        for (int ks = 0; ks < 2; ks++) {
            uint32_t af[4][4];
            #pragma unroll
            for (int mt = 0; mt < 4; mt++)
                LDSM4(af[mt][0], af[mt][1], af[mt][2], af[mt][3],
                      aB + mt * 1280 + ks * 32);
            #pragma unroll
            for (int p = 0; p < 4; p++) {
                uint32_t bf[4];
                LDSM4(bf[0], bf[1], bf[2], bf[3], bB + p * 1280 + ks * 32);
                #pragma unroll
                for (int mt = 0; mt < 4; mt++) {
                    mma_bf16(acc[mt][2 * p],     af[mt], bf[0], bf[2]);
                    mma_bf16(acc[mt][2 * p + 1], af[mt], bf[1], bf[3]);
                }
            }
        }
        __syncthreads();
    }

    #pragma unroll
    for (int mt = 0; mt < 4; mt++) {
        #pragma unroll
        for (int half = 0; half < 2; half++) {
            int row = m0 + wm * 64 + mt * 16 + (lane >> 2) + half * 8;
            size_t crow = 0;
            if (EPI == EPI_SCATTER)      crow = (size_t)win_to_flat(row) * N;
            else if (EPI != EPI_KV)      crow = (size_t)row * N;
            #pragma unroll
            for (int nt = 0; nt < 8; nt++) {
                int col = n0 + wn * 64 + nt * 8 + (lane & 3) * 2;
                float v0 = acc[mt][nt][half * 2 + 0] + bias[col];
                float v1 = acc[mt][nt][half * 2 + 1] + bias[col + 1];
                if (EPI == EPI_SCALE) { v0 *= scale; v1 *= scale; }
                if (EPI == EPI_GELU) {
                    v0 = 0.5f * v0 * (1.0f + erff(v0 * 0.70710678118654752f));
                    v1 = 0.5f * v1 * (1.0f + erff(v1 * 0.70710678118654752f));
                }
                if (EPI == EPI_SCATTER || EPI == EPI_RESID) {
                    float2 rr = *(const float2*)&R[crow + col];
                    v0 += rr.x; v1 += rr.y;
                }
                if (EPI == EPI_KV) {
                    if (col < 256) {
                        *(uint32_t*)&g_kb[(size_t)row * 256 + col] = bf2(v0, v1);
                    } else {
                        int hd = col - 256;
                        size_t base = (((size_t)(row >> 6) * 8 + (hd >> 5)) * 32
                                       + (hd & 31)) * 64 + (row & 63);
                        g_vt[base]      = __float2bfloat16(v0);
                        g_vt[base + 64] = __float2bfloat16(v1);
                    }
                } else if (OUTBF) {
                    *(uint32_t*)&bbuf(c_id)[crow + col] = bf2(v0, v1);
                } else {
                    *(float2*)&C[crow + col] = make_float2(v0, v1);
                }
            }
        }
    }
}

// ---------------------------------------------------------------------------
// Tensor-core attention: block = window (1024 blocks), warp = head.
// ---------------------------------------------------------------------------
#define AT_QOFF 0
#define AT_KOFF 33792
#define AT_VOFF 67584
#define AT_BOFF 104448
#define AT_SMEM 111744

__global__ __launch_bounds__(256) void attn_mma_k(const float* __restrict__ rpb)
{
    extern __shared__ __align__(16) char sm[];
    uint32_t u;
    asm("{ .reg .u64 t; cvta.to.shared.u64 t, %1; cvt.u32.u64 %0, t; }"
        : "=r"(u) : "l"(sm));

    int tid = threadIdx.x, lane = tid & 31, h = tid >> 5;
    int w = blockIdx.x;

    {
        const uint4* qg = (const uint4*)(g_qb + (size_t)w * 64 * 256);
        const uint4* kg = (const uint4*)(g_kb + (size_t)w * 64 * 256);
        const uint4* vg = (const uint4*)(g_vt + (size_t)w * 16384);
        #pragma unroll
        for (int i = 0; i < 8; i++) {
            int c = i * 256 + tid;
            int row = c >> 5, seg = c & 31;
            *(uint4*)(sm + AT_QOFF + row * 528 + seg * 16) = qg[c];
            *(uint4*)(sm + AT_KOFF + row * 528 + seg * 16) = kg[c];
            int vr = c >> 3, vs = c & 7;
            *(uint4*)(sm + AT_VOFF + vr * 144 + vs * 16) = vg[c];
        }
        float* bsm = (float*)(sm + AT_BOFF);
        for (int k = tid; k < 1800; k += 256) {
            int hh = k / 225, idx = k - hh * 225;
            bsm[hh * 228 + idx] = rpb[idx * 8 + hh];
        }
    }
    __syncthreads();

    int lr8 = lane & 7, lb = (lane >> 3) & 1, lk = lane >> 4;
    uint32_t rowoff = lr8 + lb * 8;
    uint32_t qb = u + AT_QOFF + rowoff * 528 + h * 64 + lk * 16;
    uint32_t kb = u + AT_KOFF + rowoff * 528 + h * 64 + lk * 16;
    uint32_t vb = u + AT_VOFF + (h * 32 + rowoff) * 144 + lk * 16;
    const float* bs = (const float*)(sm + AT_BOFF) + h * 228;

    int r0 = lane >> 2, c2 = (lane & 3) * 2;
    int wi = w & 63;
    int fR = ((wi >> 3) == 7), fC = ((wi & 7) == 7);

    #pragma unroll 1
    for (int rc = 0; rc < 4; rc++) {
        float S[8][4];
        #pragma unroll
        for (int n = 0; n < 8; n++)
            #pragma unroll
            for (int c = 0; c < 4; c++) S[n][c] = 0.0f;

        #pragma unroll
        for (int kt = 0; kt < 2; kt++) {
            uint32_t aq[4];
            LDSM4(aq[0], aq[1], aq[2], aq[3], qb + rc * 8448 + kt * 32);
            #pragma unroll
            for (int p = 0; p < 4; p++) {
                uint32_t bf[4];
                LDSM4(bf[0], bf[1], bf[2], bf[3], kb + p * 8448 + kt * 32);
                mma_bf16(S[2 * p],     aq, bf[0], bf[2]);
                mma_bf16(S[2 * p + 1], aq, bf[1], bf[3]);
            }
        }

        int i0 = rc * 16 + r0, i1 = i0 + 8;
        int ri0 = i0 >> 3, ci0 = i0 & 7, ri1 = i1 >> 3, ci1 = i1 & 7;
        int li0 = (fR ? ((ri0 < 4) ? 3 : 6) : 0) + (fC ? ((ci0 < 4) ? 1 : 2) : 0);
        int li1 = (fR ? ((ri1 < 4) ? 3 : 6) : 0) + (fC ? ((ci1 < 4) ? 1 : 2) : 0);

        float mx0 = -1e30f, mx1 = -1e30f;
        #pragma unroll
        for (int nt = 0; nt < 8; nt++) {
            #pragma unroll
            for (int cc = 0; cc < 2; cc++) {
                int j = nt * 8 + c2 + cc;
                int rj = j >> 3, cj = j & 7;
                int lj = (fR ? ((rj < 4) ? 3 : 6) : 0) + (fC ? ((cj < 4) ? 1 : 2) : 0);
                float v0 = S[nt][cc]     + bs[(ri0 - rj + 7) * 15 + (ci0 - cj + 7)];
                float v1 = S[nt][cc + 2] + bs[(ri1 - rj + 7) * 15 + (ci1 - cj + 7)];
                if (lj != li0) v0 -= 100.0f;
                if (lj != li1) v1 -= 100.0f;
                S[nt][cc] = v0; S[nt][cc + 2] = v1;
                mx0 = fmaxf(mx0, v0); mx1 = fmaxf(mx1, v1);
            }
        }
        mx0 = fmaxf(mx0, __shfl_xor_sync(0xffffffffu, mx0, 1));
        mx0 = fmaxf(mx0, __shfl_xor_sync(0xffffffffu, mx0, 2));
        mx1 = fmaxf(mx1, __shfl_xor_sync(0xffffffffu, mx1, 1));
        mx1 = fmaxf(mx1, __shfl_xor_sync(0xffffffffu, mx1, 2));

        float sum0 = 0.0f, sum1 = 0.0f;
        #pragma unroll
        for (int nt = 0; nt < 8; nt++) {
            #pragma unroll
            for (int cc = 0; cc < 2; cc++) {
                float e0 = __expf(S[nt][cc] - mx0);
                float e1 = __expf(S[nt][cc + 2] - mx1);
                S[nt][cc] = e0; S[nt][cc + 2] = e1;
                sum0 += e0; sum1 += e1;
            }
        }
        sum0 += __shfl_xor_sync(0xffffffffu, sum0, 1);
        sum0 += __shfl_xor_sync(0xffffffffu, sum0, 2);
        sum1 += __shfl_xor_sync(0xffffffffu, sum1, 1);
        sum1 += __shfl_xor_sync(0xffffffffu, sum1, 2);
        float inv0 = __fdividef(1.0f, sum0);
        float inv1 = __fdividef(1.0f, sum1);
        #pragma unroll
        for (int nt = 0; nt < 8; nt++) {
            S[nt][0] *= inv0; S[nt][1] *= inv0;
            S[nt][2] *= inv1; S[nt][3] *= inv1;
        }

        float O[4][4];
        #pragma unroll
        for (int n = 0; n < 4; n++)
            #pragma unroll
            for (int c = 0; c < 4; c++) O[n][c] = 0.0f;

        #pragma unroll
        for (int kt = 0; kt < 4; kt++) {
            uint32_t aP[4];
            aP[0] = bf2(S[2 * kt][0],     S[2 * kt][1]);
            aP[1] = bf2(S[2 * kt][2],     S[2 * kt][3]);
            aP[2] = bf2(S[2 * kt + 1][0], S[2 * kt + 1][1]);
            aP[3] = bf2(S[2 * kt + 1][2], S[2 * kt + 1][3]);
            #pragma unroll
            for (int dp = 0; dp < 2; dp++) {
                uint32_t bf[4];
                LDSM4(bf[0], bf[1], bf[2], bf[3], vb + dp * 2304 + kt * 32);
                mma_bf16(O[2 * dp],     aP, bf[0], bf[2]);
                mma_bf16(O[2 * dp + 1], aP, bf[1], bf[3]);
            }
        }

        #pragma unroll
        for (int nt = 0; nt < 4; nt++) {
            int col = h * 32 + nt * 8 + c2;
            *(uint32_t*)&g_o[(size_t)(w * 64 + i0) * 256 + col] = bf2(O[nt][0], O[nt][1]);
            *(uint32_t*)&g_o[(size_t)(w * 64 + i1) * 256 + col] = bf2(O[nt][2], O[nt][3]);
        }
    }
}

// ---------------------------------------------------------------------------
// launch
// ---------------------------------------------------------------------------
extern "C" void kernel_launch(void* const* d_in, const int* in_sizes, int n_in,
                              void* d_out, int out_size)
{
    const float* x0   = (const float*)d_in[0];
    const float* x1   = (const float*)d_in[1];
    const float* g1_0 = (const float*)d_in[2];
    const float* b1_0 = (const float*)d_in[3];
    const float* g1_1 = (const float*)d_in[4];
    const float* b1_1 = (const float*)d_in[5];
    const float* Wq   = (const float*)d_in[6];
    const float* bq   = (const float*)d_in[7];
    const float* Wkv  = (const float*)d_in[8];
    const float* bkv  = (const float*)d_in[9];
    const float* rpb  = (const float*)d_in[10];
    const float* Wp   = (const float*)d_in[11];
    const float* bp   = (const float*)d_in[12];
    const float* g2   = (const float*)d_in[13];
    const float* b2   = (const float*)d_in[14];
    const float* Wfc1 = (const float*)d_in[15];
    const float* bfc1 = (const float*)d_in[16];
    const float* Wfc2 = (const float*)d_in[17];
    const float* bfc2 = (const float*)d_in[18];
    float* out = (float*)d_out;

    cudaFuncSetAttribute(attn_mma_k, cudaFuncAttributeMaxDynamicSharedMemorySize, AT_SMEM);

    // 0) weights -> bf16 scratch
    cvt_w_k<<<768, 256>>>(Wq, Wkv, Wp, Wfc1, Wfc2);

    // 1) LN(x0), LN(x1) + shift + window partition
    ln_win_k<<<16384, 256>>>(x0, x1, g1_0, b1_0, g1_1, b1_1);

    // 2) Q = (x1w @ Wq^T + bq) * scale -> g_qb (bf16)
    gemm_tc<EPI_SCALE, true><<<dim3(2, 512), 128>>>(1, WOFF_Q, bq, -1, nullptr,
                                                    2, nullptr, 256, 256, SCALE_Q);
    // 3) K -> g_kb, V -> g_vt (transposed per window/head)
    gemm_tc<EPI_KV, false><<<dim3(4, 512), 128>>>(0, WOFF_KV, bkv, -1, nullptr,
                                                  -1, nullptr, 512, 256, 1.0f);
    // 4) attention (tensor-core) -> g_o (bf16)
    attn_mma_k<<<1024, 256, AT_SMEM>>>(rpb);

    // 5) x = x1 + scatter(attn_out @ Wp^T + bp) -> g_x (fp32)
    gemm_tc<EPI_SCATTER, false><<<dim3(2, 512), 128>>>(4, WOFF_P, bp, -1, x1,
                                                       5, nullptr, 256, 256, 1.0f);
    // 6) xn = LN2(x) -> g_xn (bf16)
    ln2_k<<<8192, 256>>>(g2, b2);

    // 7) h = gelu(xn @ Wfc1^T + bfc1) -> g_h (bf16)
    gemm_tc<EPI_GELU, true><<<dim3(8, 512), 128>>>(6, WOFF_FC1, bfc1, -1, nullptr,
                                                   7, nullptr, 1024, 256, 1.0f);
    // 8) out = x + h @ Wfc2^T + bfc2 -> d_out (fp32)
    gemm_tc<EPI_RESID, false><<<dim3(2, 512), 128>>>(7, WOFF_FC2, bfc2, 5, nullptr,
                                                     -1, out, 256, 1024, 1.0f);
}